// round 15
// baseline (speedup 1.0000x reference)
#include <cuda_runtime.h>
#include <cuda_fp16.h>
#include <cstdint>
#include <cstddef>

// ---------------------------------------------------------------------------
// LSTM_87351044866551  (Round 15 = R14 + ONE change: GEMM M-tile 128 -> 64)
//   P: transpose Wi -> g_wh fp16 [N=512][K=2048]                 (unchanged)
//   G: xg = x16 @ W16, HMMA fp16 single-term; CTA 64x256, 512 thr,
//      warp 16x64, K-chunk 64, 2-stage. 1024 CTAs -> ~1% wave tail.
//      A DRAM traffic unchanged; only L2-resident B is re-read more.
//   L: LSTM v7 (exact R14 version — 48/80 u-split, FFMA2)        (unchanged)
// ---------------------------------------------------------------------------

#define M_DIM 32768
#define N_DIM 512
#define K_DIM 2048

__device__ float g_xg[(size_t)M_DIM * N_DIM];            // 64 MB scratch
__device__ __align__(256) __half g_wh[(size_t)N_DIM * K_DIM];

// ===========================================================================
// helpers (base ISA only — tcgen05 not assemblable on this harness)
// ===========================================================================
__device__ __forceinline__ uint32_t smem_u32(const void* p) {
    uint32_t a;
    asm("{ .reg .u64 t; cvta.to.shared.u64 t, %1; cvt.u32.u64 %0, t; }"
        : "=r"(a) : "l"(p));
    return a;
}
__device__ __forceinline__ void ldsm_x4(uint32_t& r0, uint32_t& r1,
                                        uint32_t& r2, uint32_t& r3,
                                        uint32_t addr) {
    asm volatile("ldmatrix.sync.aligned.m8n8.x4.shared.b16 {%0,%1,%2,%3},[%4];"
                 : "=r"(r0), "=r"(r1), "=r"(r2), "=r"(r3) : "r"(addr));
}
__device__ __forceinline__ void mma_f16(float* d, const uint32_t* a,
                                        uint32_t b0, uint32_t b1) {
    asm volatile(
        "mma.sync.aligned.m16n8k16.row.col.f32.f16.f16.f32 "
        "{%0,%1,%2,%3},{%4,%5,%6,%7},{%8,%9},{%0,%1,%2,%3};"
        : "+f"(d[0]), "+f"(d[1]), "+f"(d[2]), "+f"(d[3])
        : "r"(a[0]), "r"(a[1]), "r"(a[2]), "r"(a[3]), "r"(b0), "r"(b1));
}
#define CPASYNC16(dst, src) \
    asm volatile("cp.async.cg.shared.global [%0],[%1],16;" :: "r"(dst), "l"(src))
#define CPCOMMIT() asm volatile("cp.async.commit_group;" ::: "memory")
#define CPWAIT0()  asm volatile("cp.async.wait_group 0;" ::: "memory")

// packed dual-fp32 FMA: d = a*b + d (lanewise) — FFMA2
__device__ __forceinline__ void ffma2(unsigned long long& d,
                                      unsigned long long a,
                                      unsigned long long b) {
    asm("fma.rn.f32x2 %0, %1, %2, %0;" : "+l"(d) : "l"(a), "l"(b));
}
__device__ __forceinline__ float f2_sum(unsigned long long d) {
    float lo, hi;
    asm("mov.b64 {%0,%1}, %2;" : "=f"(lo), "=f"(hi) : "l"(d));
    return lo + hi;
}

// ===========================================================================
// Kernel P: Wh[n][k] = fp16(Wi[k][n])
// ===========================================================================
__global__ __launch_bounds__(1024) void prep_w(const float* __restrict__ Wi) {
    __shared__ float t[32][33];
    const int k = blockIdx.x * 32 + threadIdx.y;
    const int n = blockIdx.y * 32 + threadIdx.x;
    t[threadIdx.y][threadIdx.x] = Wi[(size_t)k * N_DIM + n];
    __syncthreads();
    const int n2 = blockIdx.y * 32 + threadIdx.y;
    const int k2 = blockIdx.x * 32 + threadIdx.x;
    g_wh[(size_t)n2 * K_DIM + k2] = __float2half_rn(t[threadIdx.x][threadIdx.y]);
}

// ===========================================================================
// Kernel G: HMMA fp16 GEMM (1 term), CTA 64x256, 512 thr, warp 16x64,
// K-chunk 64, 2-stage. Stage: A@0 (64x144=9216), B@9216 (256x144) = 46080 B.
// ===========================================================================
#define SROWB 144
#define B_OFF 9216
#define STAGE_BYTES 46080
#define GEMM_SMEM (2 * STAGE_BYTES)   // 92160
#define NCHUNK 32                     // K / 64

__global__ __launch_bounds__(512, 1) void gemm_hmma(const float* __restrict__ x) {
    extern __shared__ __half smb[];
    const uint32_t sbase = smem_u32(smb);
    const int tid  = threadIdx.x;
    const int lane = tid & 31;
    const int w    = tid >> 5;
    const int wm   = w & 3;          // 4 M-warps of 16 rows
    const int wn   = w >> 2;         // 4 N-warps of 64 cols
    const int m0   = blockIdx.y * 64;
    const int n0   = blockIdx.x * 256;

    float acc[8][4];
#pragma unroll
    for (int b = 0; b < 8; b++)
#pragma unroll
        for (int c = 0; c < 4; c++) acc[b][c] = 0.f;

    const float* xA = x + (size_t)m0 * K_DIM;
    const __half* bW = g_wh + (size_t)n0 * K_DIM;

    float4 av[2];

    // A: 64 rows x 16 float4 = 1024 float4 per chunk -> 2 per thread
#define LDG_A(kt)                                                              \
    do {                                                                       \
        _Pragma("unroll")                                                      \
        for (int i = 0; i < 2; i++) {                                          \
            const int idx = tid + i * 512;                                     \
            const int r = idx >> 4, f4 = idx & 15;                             \
            av[i] = *(const float4*)(xA + (size_t)r * K_DIM + (kt) * 64 + f4 * 4); \
        }                                                                      \
    } while (0)

#define STS_A(s)                                                               \
    do {                                                                       \
        _Pragma("unroll")                                                      \
        for (int i = 0; i < 2; i++) {                                          \
            const int idx = tid + i * 512;                                     \
            const int r = idx >> 4, f4 = idx & 15;                             \
            const float4 v = av[i];                                            \
            __half2 p01, p23;                                                  \
            p01.x = __float2half_rn(v.x); p01.y = __float2half_rn(v.y);        \
            p23.x = __float2half_rn(v.z); p23.y = __float2half_rn(v.w);        \
            uint2 hp;                                                          \
            hp.x = *(uint32_t*)&p01; hp.y = *(uint32_t*)&p23;                  \
            *(uint2*)((char*)smb + (s) * STAGE_BYTES + r * SROWB + f4 * 8) = hp; \
        }                                                                      \
    } while (0)

    // B: 256 rows x 8 16B-units per chunk = 2048 units -> 4 per thread
#define CPA_B(kt, s)                                                           \
    do {                                                                       \
        _Pragma("unroll")                                                      \
        for (int i = 0; i < 4; i++) {                                          \
            const int idx = tid + i * 512;                                     \
            const int n = idx >> 3, ku = idx & 7;                              \
            const size_t gsrc = (size_t)n * K_DIM + (kt) * 64 + ku * 8;        \
            const uint32_t d =                                                 \
                sbase + (s) * STAGE_BYTES + B_OFF + n * SROWB + ku * 16;       \
            CPASYNC16(d, bW + gsrc);                                           \
        }                                                                      \
    } while (0)

    // prologue: chunk 0 into stage 0
    CPA_B(0, 0);
    CPCOMMIT();
    LDG_A(0);
    STS_A(0);
    CPWAIT0();
    __syncthreads();

    const int a_row = (lane & 7) + ((lane >> 3) & 1) * 8;
    const int a_kb  = ((lane >> 4) & 1) * 16;
    const int b_row = (lane & 7) + ((lane >> 4) & 1) * 8;
    const int b_kb  = ((lane >> 3) & 1) * 16;

    for (int kt = 0; kt < NCHUNK; kt++) {
        const int s = kt & 1;
        const bool more = (kt + 1 < NCHUNK);
        if (more) {
            CPA_B(kt + 1, s ^ 1);
            CPCOMMIT();
            LDG_A(kt + 1);
        }

        const uint32_t stg = sbase + s * STAGE_BYTES;
        // ---- first half: kk = 0,1 ----
#pragma unroll
        for (int kk = 0; kk < 2; kk++) {
            uint32_t ah[4];
            {
                const uint32_t aaddr =
                    stg + (wm * 16 + a_row) * SROWB + kk * 32 + a_kb;
                ldsm_x4(ah[0], ah[1], ah[2], ah[3], aaddr);
            }
#pragma unroll
            for (int np = 0; np < 4; np++) {
                const uint32_t baddr = stg + B_OFF +
                    (wn * 64 + np * 16 + b_row) * SROWB + kk * 32 + b_kb;
                uint32_t b0, b1, b2, b3;
                ldsm_x4(b0, b1, b2, b3, baddr);
                mma_f16(acc[np * 2],     ah, b0, b1);
                mma_f16(acc[np * 2 + 1], ah, b2, b3);
            }
        }
        if (more) STS_A(s ^ 1);   // stage s^1 free since sync at end of kt-1
        // ---- second half: kk = 2,3 ----
#pragma unroll
        for (int kk = 2; kk < 4; kk++) {
            uint32_t ah[4];
            {
                const uint32_t aaddr =
                    stg + (wm * 16 + a_row) * SROWB + kk * 32 + a_kb;
                ldsm_x4(ah[0], ah[1], ah[2], ah[3], aaddr);
            }
#pragma unroll
            for (int np = 0; np < 4; np++) {
                const uint32_t baddr = stg + B_OFF +
                    (wn * 64 + np * 16 + b_row) * SROWB + kk * 32 + b_kb;
                uint32_t b0, b1, b2, b3;
                ldsm_x4(b0, b1, b2, b3, baddr);
                mma_f16(acc[np * 2],     ah, b0, b1);
                mma_f16(acc[np * 2 + 1], ah, b2, b3);
            }
        }
        if (more) CPWAIT0();
        __syncthreads();
    }
#undef LDG_A
#undef STS_A
#undef CPA_B

    // epilogue
#pragma unroll
    for (int ni = 0; ni < 8; ni++) {
        const int row = m0 + wm * 16 + (lane >> 2);
        const int col = n0 + wn * 64 + ni * 8 + (lane & 3) * 2;
        float* p = g_xg + (size_t)row * N_DIM + col;
        float2 v0, v1;
        v0.x = acc[ni][0]; v0.y = acc[ni][1];
        v1.x = acc[ni][2]; v1.y = acc[ni][3];
        *(float2*)p = v0;
        *(float2*)(p + 8 * N_DIM) = v1;
    }
}

// ===========================================================================
// Kernel L: LSTM v7 (exact R14 version) — 48/80 u-split, FFMA2
// ===========================================================================
__device__ __forceinline__ float fsig(float x) { return 1.f / (1.f + __expf(-x)); }
__device__ __forceinline__ float ftanh(float x) { return 1.f - 2.f / (__expf(2.f * x) + 1.f); }

#define USTRIDE 52
#define US_FLOATS (512 * USTRIDE)
#define SM2_FLOATS (US_FLOATS + 256 + 1024)

__global__ __launch_bounds__(512) void lstm_rec(const float* __restrict__ Uh,
                                                const float* __restrict__ bias,
                                                const float* __restrict__ Wout,
                                                const float* __restrict__ bout,
                                                float* __restrict__ out) {
    extern __shared__ float smf[];
    float* Us = smf;                 // [512][52], Uh rows 0..47 per column
    float* hs = smf + US_FLOATS;     // [2][128]
    float* zs = hs + 256;            // [2][512]

    const int tid = threadIdx.x;
    const int g   = tid;
    const int b0  = blockIdx.x * 2;

    for (int k = 0; k < 48; k++) Us[g * USTRIDE + k] = Uh[k * 512 + g];
    unsigned long long wpk[40];
#pragma unroll
    for (int r = 0; r < 40; r++) {
        const float e = Uh[(48 + 2 * r) * 512 + g];
        const float o = Uh[(48 + 2 * r + 1) * 512 + g];
        asm("mov.b64 %0,{%1,%2};" : "=l"(wpk[r]) : "f"(e), "f"(o));
    }
    const float bg   = bias[g];
    const int  gate  = g >> 7;

    if (tid < 256) hs[tid] = 0.f;
    float c = 0.f;
    __syncthreads();

    const float* xp0 = g_xg + ((size_t)b0 * 128) * 512 + g;
    const float* xp1 = g_xg + ((size_t)(b0 + 1) * 128) * 512 + g;
    float x0 = xp0[0];
    float x1 = xp1[0];

    const ulonglong2* uv2 = (const ulonglong2*)(Us + g * USTRIDE);
    const ulonglong2* hA2 = (const ulonglong2*)hs;
    const ulonglong2* hB2 = (const ulonglong2*)(hs + 128);

    for (int t = 0; t < 128; t++) {
        unsigned long long z0a = 0ull, z0b = 0ull;
        unsigned long long z1a = 0ull, z1b = 0ull;
#pragma unroll
        for (int q = 0; q < 12; q++) {
            const ulonglong2 u = uv2[q];
            const ulonglong2 a = hA2[q];
            const ulonglong2 b = hB2[q];
            ffma2(z0a, u.x, a.x); ffma2(z0b, u.y, a.y);
            ffma2(z1a, u.x, b.x); ffma2(z1b, u.y, b.y);
        }
#pragma unroll
        for (int q = 0; q < 20; q++) {
            const ulonglong2 a = hA2[12 + q];
            const ulonglong2 b = hB2[12 + q];
            ffma2(z0a, wpk[2 * q], a.x); ffma2(z0b, wpk[2 * q + 1], a.y);
            ffma2(z1a, wpk[2 * q], b.x); ffma2(z1b, wpk[2 * q + 1], b.y);
        }
        float z0 = x0 + bg + f2_sum(z0a) + f2_sum(z0b);
        float z1 = x1 + bg + f2_sum(z1a) + f2_sum(z1b);
        if (t + 1 < 128) {
            x0 = xp0[(t + 1) * 512];
            x1 = xp1[(t + 1) * 512];
        }

        float a0, a1;
        if (gate == 2) { a0 = ftanh(z0); a1 = ftanh(z1); }
        else           { a0 = fsig(z0);  a1 = fsig(z1);  }
        zs[g]       = a0;
        zs[512 + g] = a1;
        __syncthreads();

        if (tid < 256) {
            const int bl = tid >> 7;
            const int jj = tid & 127;
            const float* zb = zs + bl * 512;
            const float ig = zb[jj];
            const float fg = zb[128 + jj];
            const float gg = zb[256 + jj];
            const float og = zb[384 + jj];
            c = fg * c + ig * gg;
            hs[bl * 128 + jj] = og * ftanh(c);
        }
        __syncthreads();
    }

    if (tid < 256) {
        const int bl = tid >> 7;
        const int jj = tid & 127;
        const float h = hs[bl * 128 + jj];
        float p0 = h * Wout[jj * 2 + 0];
        float p1 = h * Wout[jj * 2 + 1];
#pragma unroll
        for (int off = 16; off > 0; off >>= 1) {
            p0 += __shfl_down_sync(0xffffffffu, p0, off);
            p1 += __shfl_down_sync(0xffffffffu, p1, off);
        }
        if ((tid & 31) == 0) {
            const int w = tid >> 5;
            zs[w * 2 + 0] = p0;
            zs[w * 2 + 1] = p1;
        }
    }
    __syncthreads();
    if (tid < 2) {
        float s0 = bout[0], s1 = bout[1];
#pragma unroll
        for (int w = 0; w < 4; w++) {
            s0 += zs[(tid * 4 + w) * 2 + 0];
            s1 += zs[(tid * 4 + w) * 2 + 1];
        }
        out[(b0 + tid) * 2 + 0] = s0;
        out[(b0 + tid) * 2 + 1] = s1;
    }
}

// ===========================================================================
extern "C" void kernel_launch(void* const* d_in, const int* in_sizes, int n_in,
                              void* d_out, int out_size) {
    const float* x    = (const float*)d_in[0];
    const float* Wi   = (const float*)d_in[1];
    const float* Uh   = (const float*)d_in[2];
    const float* b    = (const float*)d_in[3];
    const float* Wout = (const float*)d_in[4];
    const float* bout = (const float*)d_in[5];
    float* out = (float*)d_out;

    dim3 gp(K_DIM / 32, N_DIM / 32);
    prep_w<<<gp, dim3(32, 32)>>>(Wi);

    cudaFuncSetAttribute(gemm_hmma, cudaFuncAttributeMaxDynamicSharedMemorySize,
                         GEMM_SMEM);
    dim3 gg(N_DIM / 256, M_DIM / 64);           // (2, 512) = 1024 CTAs
    gemm_hmma<<<gg, 512, GEMM_SMEM>>>(x);

    const size_t smem2 = SM2_FLOATS * sizeof(float);
    cudaFuncSetAttribute(lstm_rec, cudaFuncAttributeMaxDynamicSharedMemorySize,
                         (int)smem2);
    lstm_rec<<<128, 512, smem2>>>(Uh, b, Wout, bout, out);
}

// round 16
// speedup vs baseline: 1.1373x; 1.1373x over previous
#include <cuda_runtime.h>
#include <cuda_fp16.h>
#include <cstdint>
#include <cstddef>

// ---------------------------------------------------------------------------
// LSTM_87351044866551  (Round 16 = R14 + ONE change: GEMM K-chunk 64 -> 128)
//   P: transpose Wi -> g_wh fp16 [N=512][K=2048]                 (unchanged)
//   G: xg = x16 @ W16, HMMA fp16 single-term; CTA 128x256, 512 thr,
//      warp 32x64, K-chunk 128 (16 iterations), 2-stage, A in 4 quarters.
//   L: LSTM v7 (exact R14 version — 48/80 u-split, FFMA2)        (unchanged)
// ---------------------------------------------------------------------------

#define M_DIM 32768
#define N_DIM 512
#define K_DIM 2048

__device__ float g_xg[(size_t)M_DIM * N_DIM];            // 64 MB scratch
__device__ __align__(256) __half g_wh[(size_t)N_DIM * K_DIM];

// ===========================================================================
// helpers (base ISA only — tcgen05 not assemblable on this harness)
// ===========================================================================
__device__ __forceinline__ uint32_t smem_u32(const void* p) {
    uint32_t a;
    asm("{ .reg .u64 t; cvta.to.shared.u64 t, %1; cvt.u32.u64 %0, t; }"
        : "=r"(a) : "l"(p));
    return a;
}
__device__ __forceinline__ void ldsm_x4(uint32_t& r0, uint32_t& r1,
                                        uint32_t& r2, uint32_t& r3,
                                        uint32_t addr) {
    asm volatile("ldmatrix.sync.aligned.m8n8.x4.shared.b16 {%0,%1,%2,%3},[%4];"
                 : "=r"(r0), "=r"(r1), "=r"(r2), "=r"(r3) : "r"(addr));
}
__device__ __forceinline__ void mma_f16(float* d, const uint32_t* a,
                                        uint32_t b0, uint32_t b1) {
    asm volatile(
        "mma.sync.aligned.m16n8k16.row.col.f32.f16.f16.f32 "
        "{%0,%1,%2,%3},{%4,%5,%6,%7},{%8,%9},{%0,%1,%2,%3};"
        : "+f"(d[0]), "+f"(d[1]), "+f"(d[2]), "+f"(d[3])
        : "r"(a[0]), "r"(a[1]), "r"(a[2]), "r"(a[3]), "r"(b0), "r"(b1));
}
#define CPASYNC16(dst, src) \
    asm volatile("cp.async.cg.shared.global [%0],[%1],16;" :: "r"(dst), "l"(src))
#define CPCOMMIT() asm volatile("cp.async.commit_group;" ::: "memory")
#define CPWAIT0()  asm volatile("cp.async.wait_group 0;" ::: "memory")

// packed dual-fp32 FMA: d = a*b + d (lanewise) — FFMA2
__device__ __forceinline__ void ffma2(unsigned long long& d,
                                      unsigned long long a,
                                      unsigned long long b) {
    asm("fma.rn.f32x2 %0, %1, %2, %0;" : "+l"(d) : "l"(a), "l"(b));
}
__device__ __forceinline__ float f2_sum(unsigned long long d) {
    float lo, hi;
    asm("mov.b64 {%0,%1}, %2;" : "=f"(lo), "=f"(hi) : "l"(d));
    return lo + hi;
}

// ===========================================================================
// Kernel P: Wh[n][k] = fp16(Wi[k][n])
// ===========================================================================
__global__ __launch_bounds__(1024) void prep_w(const float* __restrict__ Wi) {
    __shared__ float t[32][33];
    const int k = blockIdx.x * 32 + threadIdx.y;
    const int n = blockIdx.y * 32 + threadIdx.x;
    t[threadIdx.y][threadIdx.x] = Wi[(size_t)k * N_DIM + n];
    __syncthreads();
    const int n2 = blockIdx.y * 32 + threadIdx.y;
    const int k2 = blockIdx.x * 32 + threadIdx.x;
    g_wh[(size_t)n2 * K_DIM + k2] = __float2half_rn(t[threadIdx.x][threadIdx.y]);
}

// ===========================================================================
// Kernel G: HMMA fp16 GEMM (1 term), CTA 128x256, 512 thr, warp 32x64,
// K-chunk 128, 2-stage. Row stride 272 = 256 data + 16 pad (conflict-free:
// bank phase 4r mod 32, same as stride 144).
// Stage: A@0 (128x272 = 34816), B@34816 (256x272 = 69632) = 104448 B.
// ===========================================================================
#define SROWB 272
#define B_OFF 34816
#define STAGE_BYTES 104448
#define GEMM_SMEM (2 * STAGE_BYTES)   // 208896
#define NCHUNK 16                     // K / 128

__global__ __launch_bounds__(512, 1) void gemm_hmma(const float* __restrict__ x) {
    extern __shared__ __half smb[];
    const uint32_t sbase = smem_u32(smb);
    const int tid  = threadIdx.x;
    const int lane = tid & 31;
    const int w    = tid >> 5;
    const int wm   = w & 3;          // 4 M-warps of 32 rows
    const int wn   = w >> 2;         // 4 N-warps of 64 cols
    const int m0   = blockIdx.y * 128;
    const int n0   = blockIdx.x * 256;

    float acc[2][8][4];
#pragma unroll
    for (int a = 0; a < 2; a++)
#pragma unroll
        for (int b = 0; b < 8; b++)
#pragma unroll
            for (int c = 0; c < 4; c++) acc[a][b][c] = 0.f;

    const float* xA = x + (size_t)m0 * K_DIM;
    const __half* bW = g_wh + (size_t)n0 * K_DIM;

    float4 av[2];

    // A quarter-load: 4096 float4/chunk (128 rows x 32 f4) -> 4 quarters x
    // 2/thread. idx = tid + i*512 + q*1024; r = idx>>5, f4 = idx&31.
#define LDG_AQ(kt, q)                                                          \
    do {                                                                       \
        _Pragma("unroll")                                                      \
        for (int i = 0; i < 2; i++) {                                          \
            const int idx = tid + i * 512 + (q) * 1024;                        \
            const int r = idx >> 5, f4 = idx & 31;                             \
            av[i] = *(const float4*)(xA + (size_t)r * K_DIM + (kt) * 128 + f4 * 4); \
        }                                                                      \
    } while (0)

#define STS_AQ(s, q)                                                           \
    do {                                                                       \
        _Pragma("unroll")                                                      \
        for (int i = 0; i < 2; i++) {                                          \
            const int idx = tid + i * 512 + (q) * 1024;                        \
            const int r = idx >> 5, f4 = idx & 31;                             \
            const float4 v = av[i];                                            \
            __half2 p01, p23;                                                  \
            p01.x = __float2half_rn(v.x); p01.y = __float2half_rn(v.y);        \
            p23.x = __float2half_rn(v.z); p23.y = __float2half_rn(v.w);        \
            uint2 hp;                                                          \
            hp.x = *(uint32_t*)&p01; hp.y = *(uint32_t*)&p23;                  \
            *(uint2*)((char*)smb + (s) * STAGE_BYTES + r * SROWB + f4 * 8) = hp; \
        }                                                                      \
    } while (0)

    // B: 256 rows x 16 16B-units per chunk = 4096 units -> 8 per thread
#define CPA_B(kt, s)                                                           \
    do {                                                                       \
        _Pragma("unroll")                                                      \
        for (int i = 0; i < 8; i++) {                                          \
            const int idx = tid + i * 512;                                     \
            const int n = idx >> 4, ku = idx & 15;                             \
            const size_t gsrc = (size_t)n * K_DIM + (kt) * 128 + ku * 8;       \
            const uint32_t d =                                                 \
                sbase + (s) * STAGE_BYTES + B_OFF + n * SROWB + ku * 16;       \
            CPASYNC16(d, bW + gsrc);                                           \
        }                                                                      \
    } while (0)

    // prologue: chunk 0 into stage 0
    CPA_B(0, 0);
    CPCOMMIT();
#pragma unroll
    for (int q = 0; q < 4; q++) {
        LDG_AQ(0, q);
        STS_AQ(0, q);
    }
    CPWAIT0();
    __syncthreads();

    const int a_row = (lane & 7) + ((lane >> 3) & 1) * 8;
    const int a_kb  = ((lane >> 4) & 1) * 16;
    const int b_row = (lane & 7) + ((lane >> 4) & 1) * 8;
    const int b_kb  = ((lane >> 3) & 1) * 16;

    for (int kt = 0; kt < NCHUNK; kt++) {
        const int s = kt & 1;
        const bool more = (kt + 1 < NCHUNK);
        if (more) {
            CPA_B(kt + 1, s ^ 1);
            CPCOMMIT();
            LDG_AQ(kt + 1, 0);
        }

        const uint32_t stg = sbase + s * STAGE_BYTES;
        // 8 kk-halves; STS a quarter after kk = 1, 3, 5; final after kk = 7
#pragma unroll
        for (int kk = 0; kk < 8; kk++) {
            uint32_t ah[2][4];
#pragma unroll
            for (int mi = 0; mi < 2; mi++) {
                const uint32_t aaddr =
                    stg + (wm * 32 + mi * 16 + a_row) * SROWB + kk * 32 + a_kb;
                ldsm_x4(ah[mi][0], ah[mi][1], ah[mi][2], ah[mi][3], aaddr);
            }
#pragma unroll
            for (int np = 0; np < 4; np++) {
                const uint32_t baddr = stg + B_OFF +
                    (wn * 64 + np * 16 + b_row) * SROWB + kk * 32 + b_kb;
                uint32_t b0, b1, b2, b3;
                ldsm_x4(b0, b1, b2, b3, baddr);
#pragma unroll
                for (int mi = 0; mi < 2; mi++) {
                    mma_f16(acc[mi][np * 2],     ah[mi], b0, b1);
                    mma_f16(acc[mi][np * 2 + 1], ah[mi], b2, b3);
                }
            }
            if (more && (kk & 1) && kk < 7) {
                const int q = kk >> 1;          // 0,1,2 after kk=1,3,5
                STS_AQ(s ^ 1, q);
                LDG_AQ(kt + 1, q + 1);
            }
        }
        if (more) {
            STS_AQ(s ^ 1, 3);
            CPWAIT0();
        }
        __syncthreads();
    }
#undef LDG_AQ
#undef STS_AQ
#undef CPA_B

    // epilogue
#pragma unroll
    for (int mi = 0; mi < 2; mi++)
#pragma unroll
        for (int ni = 0; ni < 8; ni++) {
            const int row = m0 + wm * 32 + mi * 16 + (lane >> 2);
            const int col = n0 + wn * 64 + ni * 8 + (lane & 3) * 2;
            float* p = g_xg + (size_t)row * N_DIM + col;
            float2 v0, v1;
            v0.x = acc[mi][ni][0]; v0.y = acc[mi][ni][1];
            v1.x = acc[mi][ni][2]; v1.y = acc[mi][ni][3];
            *(float2*)p = v0;
            *(float2*)(p + 8 * N_DIM) = v1;
        }
}

// ===========================================================================
// Kernel L: LSTM v7 (exact R14 version) — 48/80 u-split, FFMA2
// ===========================================================================
__device__ __forceinline__ float fsig(float x) { return 1.f / (1.f + __expf(-x)); }
__device__ __forceinline__ float ftanh(float x) { return 1.f - 2.f / (__expf(2.f * x) + 1.f); }

#define USTRIDE 52
#define US_FLOATS (512 * USTRIDE)
#define SM2_FLOATS (US_FLOATS + 256 + 1024)

__global__ __launch_bounds__(512) void lstm_rec(const float* __restrict__ Uh,
                                                const float* __restrict__ bias,
                                                const float* __restrict__ Wout,
                                                const float* __restrict__ bout,
                                                float* __restrict__ out) {
    extern __shared__ float smf[];
    float* Us = smf;                 // [512][52], Uh rows 0..47 per column
    float* hs = smf + US_FLOATS;     // [2][128]
    float* zs = hs + 256;            // [2][512]

    const int tid = threadIdx.x;
    const int g   = tid;
    const int b0  = blockIdx.x * 2;

    for (int k = 0; k < 48; k++) Us[g * USTRIDE + k] = Uh[k * 512 + g];
    unsigned long long wpk[40];
#pragma unroll
    for (int r = 0; r < 40; r++) {
        const float e = Uh[(48 + 2 * r) * 512 + g];
        const float o = Uh[(48 + 2 * r + 1) * 512 + g];
        asm("mov.b64 %0,{%1,%2};" : "=l"(wpk[r]) : "f"(e), "f"(o));
    }
    const float bg   = bias[g];
    const int  gate  = g >> 7;

    if (tid < 256) hs[tid] = 0.f;
    float c = 0.f;
    __syncthreads();

    const float* xp0 = g_xg + ((size_t)b0 * 128) * 512 + g;
    const float* xp1 = g_xg + ((size_t)(b0 + 1) * 128) * 512 + g;
    float x0 = xp0[0];
    float x1 = xp1[0];

    const ulonglong2* uv2 = (const ulonglong2*)(Us + g * USTRIDE);
    const ulonglong2* hA2 = (const ulonglong2*)hs;
    const ulonglong2* hB2 = (const ulonglong2*)(hs + 128);

    for (int t = 0; t < 128; t++) {
        unsigned long long z0a = 0ull, z0b = 0ull;
        unsigned long long z1a = 0ull, z1b = 0ull;
#pragma unroll
        for (int q = 0; q < 12; q++) {
            const ulonglong2 u = uv2[q];
            const ulonglong2 a = hA2[q];
            const ulonglong2 b = hB2[q];
            ffma2(z0a, u.x, a.x); ffma2(z0b, u.y, a.y);
            ffma2(z1a, u.x, b.x); ffma2(z1b, u.y, b.y);
        }
#pragma unroll
        for (int q = 0; q < 20; q++) {
            const ulonglong2 a = hA2[12 + q];
            const ulonglong2 b = hB2[12 + q];
            ffma2(z0a, wpk[2 * q], a.x); ffma2(z0b, wpk[2 * q + 1], a.y);
            ffma2(z1a, wpk[2 * q], b.x); ffma2(z1b, wpk[2 * q + 1], b.y);
        }
        float z0 = x0 + bg + f2_sum(z0a) + f2_sum(z0b);
        float z1 = x1 + bg + f2_sum(z1a) + f2_sum(z1b);
        if (t + 1 < 128) {
            x0 = xp0[(t + 1) * 512];
            x1 = xp1[(t + 1) * 512];
        }

        float a0, a1;
        if (gate == 2) { a0 = ftanh(z0); a1 = ftanh(z1); }
        else           { a0 = fsig(z0);  a1 = fsig(z1);  }
        zs[g]       = a0;
        zs[512 + g] = a1;
        __syncthreads();

        if (tid < 256) {
            const int bl = tid >> 7;
            const int jj = tid & 127;
            const float* zb = zs + bl * 512;
            const float ig = zb[jj];
            const float fg = zb[128 + jj];
            const float gg = zb[256 + jj];
            const float og = zb[384 + jj];
            c = fg * c + ig * gg;
            hs[bl * 128 + jj] = og * ftanh(c);
        }
        __syncthreads();
    }

    if (tid < 256) {
        const int bl = tid >> 7;
        const int jj = tid & 127;
        const float h = hs[bl * 128 + jj];
        float p0 = h * Wout[jj * 2 + 0];
        float p1 = h * Wout[jj * 2 + 1];
#pragma unroll
        for (int off = 16; off > 0; off >>= 1) {
            p0 += __shfl_down_sync(0xffffffffu, p0, off);
            p1 += __shfl_down_sync(0xffffffffu, p1, off);
        }
        if ((tid & 31) == 0) {
            const int w = tid >> 5;
            zs[w * 2 + 0] = p0;
            zs[w * 2 + 1] = p1;
        }
    }
    __syncthreads();
    if (tid < 2) {
        float s0 = bout[0], s1 = bout[1];
#pragma unroll
        for (int w = 0; w < 4; w++) {
            s0 += zs[(tid * 4 + w) * 2 + 0];
            s1 += zs[(tid * 4 + w) * 2 + 1];
        }
        out[(b0 + tid) * 2 + 0] = s0;
        out[(b0 + tid) * 2 + 1] = s1;
    }
}

// ===========================================================================
extern "C" void kernel_launch(void* const* d_in, const int* in_sizes, int n_in,
                              void* d_out, int out_size) {
    const float* x    = (const float*)d_in[0];
    const float* Wi   = (const float*)d_in[1];
    const float* Uh   = (const float*)d_in[2];
    const float* b    = (const float*)d_in[3];
    const float* Wout = (const float*)d_in[4];
    const float* bout = (const float*)d_in[5];
    float* out = (float*)d_out;

    dim3 gp(K_DIM / 32, N_DIM / 32);
    prep_w<<<gp, dim3(32, 32)>>>(Wi);

    cudaFuncSetAttribute(gemm_hmma, cudaFuncAttributeMaxDynamicSharedMemorySize,
                         GEMM_SMEM);
    dim3 gg(N_DIM / 256, M_DIM / 128);          // (2, 256) = 512 CTAs
    gemm_hmma<<<gg, 512, GEMM_SMEM>>>(x);

    const size_t smem2 = SM2_FLOATS * sizeof(float);
    cudaFuncSetAttribute(lstm_rec, cudaFuncAttributeMaxDynamicSharedMemorySize,
                         (int)smem2);
    lstm_rec<<<128, 512, smem2>>>(Uh, b, Wout, bout, out);
}